// round 7
// baseline (speedup 1.0000x reference)
#include <cuda_runtime.h>
#include <cstdint>

#define NB 16384
#define NT 1024
#define HH 64
#define TPB 64                 // one warp-pair: 32 elements, j split 32/32
#define GRID (NB / 32)         // 512 blocks

#define L2E2 2.8853900817779268f   // 2*log2(e), folded into W1/b1/W2/b2

typedef unsigned long long u64;

// ---- packed f32x2 helpers ----
static __device__ __forceinline__ u64 fma2(u64 a, u64 b, u64 c) {
    u64 d;
    asm("fma.rn.f32x2 %0, %1, %2, %3;" : "=l"(d) : "l"(a), "l"(b), "l"(c));
    return d;
}
static __device__ __forceinline__ u64 pk(float a, float b) {
    u64 d;
    asm("mov.b64 %0, {%1, %2};" : "=l"(d) : "f"(a), "f"(b));
    return d;
}
static __device__ __forceinline__ u64 dup2(float a) {
    u64 d;
    asm("mov.b64 %0, {%1, %1};" : "=l"(d) : "f"(a));
    return d;
}
static __device__ __forceinline__ void upk(u64 v, float& a, float& b) {
    asm("mov.b64 {%0, %1}, %2;" : "=f"(a), "=f"(b) : "l"(v));
}
// tanh with prescaled arg a = 2*log2(e)*x: tanh(x) = 1 - 2/(2^a + 1).
// Validated at rel_err ~3e-7 over 1023 steps (rounds 1-5).
static __device__ __forceinline__ float tanh_pre(float a) {
    float e, r;
    asm("ex2.approx.f32 %0, %1;" : "=f"(e) : "f"(a));
    asm("rcp.approx.f32 %0, %1;" : "=f"(r) : "f"(e + 1.0f));
    return fmaf(-2.0f, r, 1.0f);
}

// ---- constant bank (filled by prep kernel + memcpy-to-symbol each launch) ----
struct __align__(16) CC {
    u64 W2pk[16][HH];      // [kk][j] = (W2[j][2kk], W2[j][2kk+1]) * L2E2, k-half 0..31
    float W1x[HH], W1y[HH], b1L[HH], b2L[HH];   // * L2E2
    float W3P[2 * HH];     // W3P[2j+d] = W3[d][j] (unscaled)
    float b3[2];
    float dtv[NT];         // dt[t] = ts[t+1] - ts[t]
};
__device__ CC g_stage;     // staging buffer written by prep kernel
__constant__ CC cc;

__device__ __constant__ float cA[5][5] = {
    {(float)(1.0 / 5.0), 0.f, 0.f, 0.f, 0.f},
    {(float)(3.0 / 40.0), (float)(9.0 / 40.0), 0.f, 0.f, 0.f},
    {(float)(44.0 / 45.0), (float)(-56.0 / 15.0), (float)(32.0 / 9.0), 0.f, 0.f},
    {(float)(19372.0 / 6561.0), (float)(-25360.0 / 2187.0),
     (float)(64448.0 / 6561.0), (float)(-212.0 / 729.0), 0.f},
    {(float)(9017.0 / 3168.0), (float)(-355.0 / 33.0),
     (float)(46732.0 / 5247.0), (float)(49.0 / 176.0),
     (float)(-5103.0 / 18656.0)},
};

__global__ void prep_kernel(const float* __restrict__ ts,
                            const float* __restrict__ W1, const float* __restrict__ b1,
                            const float* __restrict__ W2, const float* __restrict__ b2,
                            const float* __restrict__ W3, const float* __restrict__ b3) {
    const int tid = threadIdx.x;
    for (int i = tid; i < 16 * HH; i += 256) {
        const int kk = i >> 6, j = i & 63;
        const float a = W2[j * HH + 2 * kk] * L2E2;
        const float b = W2[j * HH + 2 * kk + 1] * L2E2;
        g_stage.W2pk[kk][j] = ((u64)__float_as_uint(b) << 32) | (u64)__float_as_uint(a);
    }
    for (int i = tid; i < HH; i += 256) {
        g_stage.W1x[i] = W1[2 * i] * L2E2;
        g_stage.W1y[i] = W1[2 * i + 1] * L2E2;
        g_stage.b1L[i] = b1[i] * L2E2;
        g_stage.b2L[i] = b2[i] * L2E2;
    }
    for (int i = tid; i < 2 * HH; i += 256) {
        const int d = i >> 6, j = i & 63;
        g_stage.W3P[2 * j + d] = W3[i];
    }
    if (tid < 2) g_stage.b3[tid] = b3[tid];
    for (int i = tid; i < NT; i += 256)
        g_stage.dtv[i] = (i < NT - 1) ? (ts[i + 1] - ts[i]) : 0.f;
}

// ---- layer 1: this warp's 32 units for the lane's element, into smem row ----
template <int U0>
static __device__ __forceinline__ void layer1(float sx, float sy, float* hb) {
#pragma unroll
    for (int q = 0; q < 8; q++) {
        float h[4];
#pragma unroll
        for (int r = 0; r < 4; r++) {
            const int u = U0 + 4 * q + r;   // uniform constant index
            h[r] = tanh_pre(fmaf(sx, cc.W1x[u], fmaf(sy, cc.W1y[u], cc.b1L[u])));
        }
        *(float4*)&hb[U0 + 4 * q] = make_float4(h[0], h[1], h[2], h[3]);
    }
}

// ---- layers 2+3 for this warp's 32 j's; h read per-k from the lane's row ----
template <int U0>
static __device__ __forceinline__ void l23(const float* hb, const u64* w2s,
                                           float& px, float& py) {
    u64 acc[32];
#pragma unroll
    for (int jj = 0; jj < 32; jj++) acc[jj] = pk(cc.b2L[U0 + jj], 0.f);

    // k 0..31: weights from constant (warp-uniform -> ULDC, zero crossbar)
#pragma unroll 2
    for (int kk = 0; kk < 16; kk++) {
        const u64 h = *(const u64*)&hb[2 * kk];     // lane's own h pair (LDS.64)
#pragma unroll
        for (int jj = 0; jj < 32; jj++)
            acc[jj] = fma2(h, cc.W2pk[kk][U0 + jj], acc[jj]);
    }
    // k 32..63: weights from smem, true broadcast (all lanes same address)
#pragma unroll 2
    for (int kk = 0; kk < 16; kk++) {
        const u64 h = *(const u64*)&hb[32 + 2 * kk];
        const u64* row = w2s + kk * HH + U0;
#pragma unroll
        for (int jj = 0; jj < 32; jj++)
            acc[jj] = fma2(h, row[jj], acc[jj]);
    }

    u64 accP = 0ull;
#pragma unroll
    for (int jj = 0; jj < 32; jj++) {
        float lo, hi;
        upk(acc[jj], lo, hi);
        const float g = tanh_pre(lo + hi);   // bias already in acc (prescaled)
        accP = fma2(dup2(g), *(const u64*)&cc.W3P[2 * (U0 + jj)], accP);
    }
    upk(accP, px, py);
}

__global__ void __launch_bounds__(TPB)
ode_kernel(const float* __restrict__ y0, const float* __restrict__ W2,
           float* __restrict__ out) {
    __shared__ __align__(16) u64 W2s[16][HH];      // [kk][j], k-half 32..63, x L2E2
    __shared__ __align__(16) float hbuf[32][68];   // [elem][unit], padded rows
    __shared__ float2 pbuf[2][32];                 // per-half layer-3 partials

    const int tid = threadIdx.x;
    const int lane = tid & 31;
    const int whalf = tid >> 5;        // 0: j/units 0..31, 1: 32..63

    for (int i = tid; i < 16 * HH; i += TPB) {
        const int kk = i >> 6, j = i & 63;
        const float a = W2[j * HH + 32 + 2 * kk] * L2E2;
        const float b = W2[j * HH + 33 + 2 * kk] * L2E2;
        W2s[kk][j] = pk(a, b);
    }
    __syncthreads();

    const int e = blockIdx.x * 32 + lane;
    float* hb = &hbuf[lane][0];
    const u64* w2s = &W2s[0][0];

    const float2 yv = ((const float2*)y0)[e];
    float yx = yv.x, yy = yv.y;
    float2* o2 = (float2*)out;
    if (whalf == 0) o2[e] = yv;        // SaveAt includes the initial state

    const float B1 = (float)(35.0 / 384.0);
    const float B3 = (float)(500.0 / 1113.0);
    const float B4 = (float)(125.0 / 192.0);
    const float B5 = (float)(-2187.0 / 6784.0);
    const float B6 = (float)(11.0 / 84.0);

    for (int t = 0; t < NT - 1; t++) {
        const float dtv = cc.dtv[t];
        float kxr[6], kyr[6];

#pragma unroll 1
        for (int st = 0; st < 6; st++) {
            // ---- stage input (identical on both warps; kxr from pbuf path) ----
            float sx, sy;
            if (st == 0) {
                sx = yx; sy = yy;
            } else {
                float ax = 0.f, ay = 0.f;
                for (int i = 0; i < st; i++) {
                    const float a = cA[st - 1][i];
                    ax = fmaf(a, kxr[i], ax);
                    ay = fmaf(a, kyr[i], ay);
                }
                sx = fmaf(dtv, ax, yx);
                sy = fmaf(dtv, ay, yy);
            }

            // ---- layer 1: each warp fills its unit-half of the lane's h row ----
            if (whalf == 0) layer1<0>(sx, sy, hb);
            else            layer1<32>(sx, sy, hb);
            __syncthreads();   // h rows complete; also WAR-protects pbuf

            // ---- layers 2+3 on this warp's j-half ----
            float px, py;
            if (whalf == 0) l23<0>(hb, w2s, px, py);
            else            l23<32>(hb, w2s, px, py);
            pbuf[whalf][lane] = make_float2(px, py);
            __syncthreads();   // partials complete; also WAR-protects hbuf

            const float2 pa = pbuf[0][lane];
            const float2 pb = pbuf[1][lane];
            kxr[st] = pa.x + pb.x + cc.b3[0];
            kyr[st] = pa.y + pb.y + cc.b3[1];
        }

        // ---- combine and advance (redundant on both warps) ----
        float ax = B1 * kxr[0], ay = B1 * kyr[0];
        ax = fmaf(B3, kxr[2], ax); ay = fmaf(B3, kyr[2], ay);
        ax = fmaf(B4, kxr[3], ax); ay = fmaf(B4, kyr[3], ay);
        ax = fmaf(B5, kxr[4], ax); ay = fmaf(B5, kyr[4], ay);
        ax = fmaf(B6, kxr[5], ax); ay = fmaf(B6, kyr[5], ay);
        yx = fmaf(dtv, ax, yx);
        yy = fmaf(dtv, ay, yy);
        if (whalf == 0)
            o2[(size_t)(t + 1) * NB + e] = make_float2(yx, yy);
    }
}

extern "C" void kernel_launch(void* const* d_in, const int* in_sizes, int n_in,
                              void* d_out, int out_size) {
    const float* y0 = (const float*)d_in[0];
    const float* ts = (const float*)d_in[1];
    const float* W1 = (const float*)d_in[2];
    const float* b1 = (const float*)d_in[3];
    const float* W2 = (const float*)d_in[4];
    const float* b2 = (const float*)d_in[5];
    const float* W3 = (const float*)d_in[6];
    const float* b3 = (const float*)d_in[7];

    prep_kernel<<<1, 256>>>(ts, W1, b1, W2, b2, W3, b3);

    void* src = nullptr;
    cudaGetSymbolAddress(&src, g_stage);
    cudaMemcpyToSymbolAsync(cc, src, sizeof(CC), 0, cudaMemcpyDeviceToDevice, 0);

    ode_kernel<<<GRID, TPB>>>(y0, W2, (float*)d_out);
}

// round 8
// speedup vs baseline: 1.4544x; 1.4544x over previous
#include <cuda_runtime.h>
#include <cstdint>

#define NB 16384
#define NT 1024
#define HH 64
#define TPB 64                 // warp-pair: 16 elements, j split 32/32
#define GRID (NB / 16)         // 1024 blocks -> 2048 warps

#define L2E2 2.8853900817779268f   // 2*log2(e), folded into W1/b1/W2/b2

typedef unsigned long long u64;

static __device__ __forceinline__ u64 fma2(u64 a, u64 b, u64 c) {
    u64 d;
    asm("fma.rn.f32x2 %0, %1, %2, %3;" : "=l"(d) : "l"(a), "l"(b), "l"(c));
    return d;
}
static __device__ __forceinline__ u64 pk(float a, float b) {
    u64 d;
    asm("mov.b64 %0, {%1, %2};" : "=l"(d) : "f"(a), "f"(b));
    return d;
}
static __device__ __forceinline__ u64 dup2(float a) {
    u64 d;
    asm("mov.b64 %0, {%1, %1};" : "=l"(d) : "f"(a));
    return d;
}
static __device__ __forceinline__ void upk(u64 v, float& a, float& b) {
    asm("mov.b64 {%0, %1}, %2;" : "=f"(a), "=f"(b) : "l"(v));
}
// tanh with prescaled arg a = 2*log2(e)*x: tanh(x) = 1 - 2/(2^a + 1).
static __device__ __forceinline__ float tanh_pre(float a) {
    float e, r;
    asm("ex2.approx.f32 %0, %1;" : "=f"(e) : "f"(a));
    asm("rcp.approx.f32 %0, %1;" : "=f"(r) : "f"(e + 1.0f));
    return fmaf(-2.0f, r, 1.0f);
}

__device__ __constant__ float cA[5][5] = {
    {(float)(1.0 / 5.0), 0.f, 0.f, 0.f, 0.f},
    {(float)(3.0 / 40.0), (float)(9.0 / 40.0), 0.f, 0.f, 0.f},
    {(float)(44.0 / 45.0), (float)(-56.0 / 15.0), (float)(32.0 / 9.0), 0.f, 0.f},
    {(float)(19372.0 / 6561.0), (float)(-25360.0 / 2187.0),
     (float)(64448.0 / 6561.0), (float)(-212.0 / 729.0), 0.f},
    {(float)(9017.0 / 3168.0), (float)(-355.0 / 33.0),
     (float)(46732.0 / 5247.0), (float)(49.0 / 176.0),
     (float)(-5103.0 / 18656.0)},
};

__global__ void __launch_bounds__(TPB, 7)
ode_kernel(const float* __restrict__ y0, const float* __restrict__ ts,
           const float* __restrict__ W1, const float* __restrict__ b1,
           const float* __restrict__ W2, const float* __restrict__ b2,
           const float* __restrict__ W3, const float* __restrict__ b3,
           float* __restrict__ out) {
    __shared__ __align__(16) float W2s[HH][HH];  // [k][j] * L2E2 (16 KB)
    __shared__ __align__(16) float hT[2][HH][16]; // double-buffered h (8 KB)
    __shared__ float W1x[HH], W1y[HH], b1L[HH];   // * L2E2
    __shared__ u64 b2p[HH / 2];                   // j-pair packed, * L2E2
    __shared__ u64 W3p[HH];                       // (W3[0][j], W3[1][j])
    __shared__ float2 pbuf[2][4][4];              // [jh][g][m] partials
    __shared__ float dts[NT];
    __shared__ float b3s[2];

    const int tid = threadIdx.x;
    for (int i = tid; i < HH * HH; i += TPB) {
        const int j = i >> 6, k = i & 63;
        W2s[k][j] = W2[i] * L2E2;                 // transpose
    }
    for (int i = tid; i < HH; i += TPB) {
        W1x[i] = W1[2 * i] * L2E2;
        W1y[i] = W1[2 * i + 1] * L2E2;
        b1L[i] = b1[i] * L2E2;
        W3p[i] = pk(W3[i], W3[HH + i]);
    }
    for (int i = tid; i < HH / 2; i += TPB)
        b2p[i] = pk(b2[2 * i] * L2E2, b2[2 * i + 1] * L2E2);
    if (tid < 2) b3s[tid] = b3[tid];
    for (int i = tid; i < NT - 1; i += TPB) dts[i] = ts[i + 1] - ts[i];
    __syncthreads();

    const int lane = tid & 31;
    const int jh = tid >> 5;        // warp's j-half: units/j 32*jh..
    const int o = lane & 7;
    const int g = lane >> 3;
    const int jb = 32 * jh + 4 * o; // lane's 4 units/j: jb..jb+3
    const int e0 = blockIdx.x * 16 + 4 * g;

    float yx[4], yy[4];
#pragma unroll
    for (int m = 0; m < 4; m++) {
        const float2 v = reinterpret_cast<const float2*>(y0)[e0 + m];
        yx[m] = v.x;
        yy[m] = v.y;
    }
    float2* o2 = reinterpret_cast<float2*>(out);
    if (jh == 0 && o == 0) {   // SaveAt includes the initial state
        *(float4*)&o2[e0]     = make_float4(yx[0], yy[0], yx[1], yy[1]);
        *(float4*)&o2[e0 + 2] = make_float4(yx[2], yy[2], yx[3], yy[3]);
    }

    const float B1 = (float)(35.0 / 384.0);
    const float B3 = (float)(500.0 / 1113.0);
    const float B4 = (float)(125.0 / 192.0);
    const float B5 = (float)(-2187.0 / 6784.0);
    const float B6 = (float)(11.0 / 84.0);

    for (int t = 0; t < NT - 1; t++) {
        const float dtv = dts[t];
        float kx[6][4], ky[6][4];
        float sx[4], sy[4];
#pragma unroll
        for (int m = 0; m < 4; m++) { sx[m] = yx[m]; sy[m] = yy[m]; }

#pragma unroll 1
        for (int st = 0; st < 6; st++) {
            const int buf = st & 1;

            // ---- layer 1: 4 units (scrambled by (r+o)&3 -> STS floor) ----
#pragma unroll
            for (int r = 0; r < 4; r++) {
                const int u = jb + ((r + o) & 3);
                const float wx = W1x[u], wy = W1y[u], bb = b1L[u];
                float hv[4];
#pragma unroll
                for (int m = 0; m < 4; m++)
                    hv[m] = tanh_pre(fmaf(sx[m], wx, fmaf(sy[m], wy, bb)));
                *(float4*)&hT[buf][u][4 * g] =
                    make_float4(hv[0], hv[1], hv[2], hv[3]);
            }
            __syncthreads();   // hT[buf] complete (RAW)

            // ---- layer 2: 4 j's x 4 elements over 64 k ----
            u64 acc[4][2];
            {
                const u64 bp0 = b2p[(jb >> 1)];
                const u64 bp1 = b2p[(jb >> 1) + 1];
#pragma unroll
                for (int m = 0; m < 4; m++) { acc[m][0] = bp0; acc[m][1] = bp1; }
            }
#pragma unroll 8
            for (int k = 0; k < HH; k++) {
                const float4 hv = *(const float4*)&hT[buf][k][4 * g];
                const float4 wv = *(const float4*)&W2s[k][jb];
                const u64 w0 = ((const u64*)&wv)[0];
                const u64 w1 = ((const u64*)&wv)[1];
                const u64 h0 = dup2(hv.x), h1 = dup2(hv.y);
                const u64 h2 = dup2(hv.z), h3 = dup2(hv.w);
                acc[0][0] = fma2(h0, w0, acc[0][0]);
                acc[0][1] = fma2(h0, w1, acc[0][1]);
                acc[1][0] = fma2(h1, w0, acc[1][0]);
                acc[1][1] = fma2(h1, w1, acc[1][1]);
                acc[2][0] = fma2(h2, w0, acc[2][0]);
                acc[2][1] = fma2(h2, w1, acc[2][1]);
                acc[3][0] = fma2(h3, w0, acc[3][0]);
                acc[3][1] = fma2(h3, w1, acc[3][1]);
            }

            // ---- layer-2 tanh + layer 3 partial over lane's 4 j's ----
            u64 accP[4] = {0ull, 0ull, 0ull, 0ull};
#pragma unroll
            for (int p = 0; p < 2; p++) {
                const u64 w3a = W3p[jb + 2 * p];
                const u64 w3b = W3p[jb + 2 * p + 1];
#pragma unroll
                for (int m = 0; m < 4; m++) {
                    float a0, a1;
                    upk(acc[m][p], a0, a1);
                    accP[m] = fma2(dup2(tanh_pre(a0)), w3a, accP[m]);
                    accP[m] = fma2(dup2(tanh_pre(a1)), w3b, accP[m]);
                }
            }

            // ---- reduce over 8 o-lanes; exchange j-halves via pbuf ----
            float fx[4], fy[4];
#pragma unroll
            for (int m = 0; m < 4; m++) {
                float px, py;
                upk(accP[m], px, py);
                px += __shfl_xor_sync(0xffffffffu, px, 1);
                py += __shfl_xor_sync(0xffffffffu, py, 1);
                px += __shfl_xor_sync(0xffffffffu, px, 2);
                py += __shfl_xor_sync(0xffffffffu, py, 2);
                px += __shfl_xor_sync(0xffffffffu, px, 4);
                py += __shfl_xor_sync(0xffffffffu, py, 4);
                fx[m] = px;
                fy[m] = py;
            }
            if (o == 0) {
#pragma unroll
                for (int m = 0; m < 4; m++)
                    pbuf[jh][g][m] = make_float2(fx[m], fy[m]);
            }
            __syncthreads();   // pbuf complete (RAW)

#pragma unroll
            for (int m = 0; m < 4; m++) {
                const float2 pa = pbuf[0][g][m];
                const float2 pb = pbuf[1][g][m];
                kx[st][m] = pa.x + pb.x + b3s[0];
                ky[st][m] = pa.y + pb.y + b3s[1];
            }

            if (st < 5) {  // next stage input
#pragma unroll
                for (int m = 0; m < 4; m++) {
                    float ax = 0.f, ay = 0.f;
                    for (int i = 0; i <= st; i++) {
                        const float a = cA[st][i];
                        ax = fmaf(a, kx[i][m], ax);
                        ay = fmaf(a, ky[i][m], ay);
                    }
                    sx[m] = fmaf(dtv, ax, yx[m]);
                    sy[m] = fmaf(dtv, ay, yy[m]);
                }
            }
        }

        // ---- combine and advance ----
#pragma unroll
        for (int m = 0; m < 4; m++) {
            float ax = B1 * kx[0][m], ay = B1 * ky[0][m];
            ax = fmaf(B3, kx[2][m], ax); ay = fmaf(B3, ky[2][m], ay);
            ax = fmaf(B4, kx[3][m], ax); ay = fmaf(B4, ky[3][m], ay);
            ax = fmaf(B5, kx[4][m], ax); ay = fmaf(B5, ky[4][m], ay);
            ax = fmaf(B6, kx[5][m], ax); ay = fmaf(B6, ky[5][m], ay);
            yx[m] = fmaf(dtv, ax, yx[m]);
            yy[m] = fmaf(dtv, ay, yy[m]);
        }
        if (jh == 0 && o == 0) {
            float2* orow = o2 + (size_t)(t + 1) * NB;
            *(float4*)&orow[e0]     = make_float4(yx[0], yy[0], yx[1], yy[1]);
            *(float4*)&orow[e0 + 2] = make_float4(yx[2], yy[2], yx[3], yy[3]);
        }
    }
}

extern "C" void kernel_launch(void* const* d_in, const int* in_sizes, int n_in,
                              void* d_out, int out_size) {
    const float* y0 = (const float*)d_in[0];
    const float* ts = (const float*)d_in[1];
    const float* W1 = (const float*)d_in[2];
    const float* b1 = (const float*)d_in[3];
    const float* W2 = (const float*)d_in[4];
    const float* b2 = (const float*)d_in[5];
    const float* W3 = (const float*)d_in[6];
    const float* b3 = (const float*)d_in[7];
    ode_kernel<<<GRID, TPB>>>(y0, ts, W1, b1, W2, b2, W3, b3, (float*)d_out);
}